// round 9
// baseline (speedup 1.0000x reference)
#include <cuda_runtime.h>
#include <cuda_bf16.h>
#include <cuda_fp16.h>
#include <math.h>
#include <stdint.h>

// Problem constants
#define BATCH 16
#define NPATCH 4096
#define KTOK 32
#define DIM 512
#define DHEAD 256
#define SCALE_V 0.0625f   // 256^-0.5

#define SPLITS 16

// Scratch (no allocation allowed -> device globals)
__device__ __half g_Qkh [BATCH*KTOK*DIM];
__device__ float  g_Gp  [SPLITS*BATCH*KTOK*DIM];
__device__ float  g_G   [BATCH*KTOK*DIM];
__device__ float  g_rows[BATCH*KTOK*SPLITS];

// ---------------------------------------------------------------------------

#define LDSM4(R0,R1,R2,R3,ADDR) \
    asm volatile("ldmatrix.sync.aligned.m8n8.x4.shared.b16 {%0,%1,%2,%3}, [%4];" \
        : "=r"(R0),"=r"(R1),"=r"(R2),"=r"(R3) : "r"(ADDR))

#define LDSM4T(R0,R1,R2,R3,ADDR) \
    asm volatile("ldmatrix.sync.aligned.m8n8.x4.trans.shared.b16 {%0,%1,%2,%3}, [%4];" \
        : "=r"(R0),"=r"(R1),"=r"(R2),"=r"(R3) : "r"(ADDR))

#define MMA_F16(C,A,B0,B1) \
    asm volatile("mma.sync.aligned.m16n8k16.row.col.f32.f16.f16.f32 " \
        "{%0,%1,%2,%3},{%4,%5,%6,%7},{%8,%9},{%0,%1,%2,%3};" \
        : "+f"((C)[0]),"+f"((C)[1]),"+f"((C)[2]),"+f"((C)[3]) \
        : "r"((A)[0]),"r"((A)[1]),"r"((A)[2]),"r"((A)[3]),"r"(B0),"r"(B1))

__device__ __forceinline__ uint32_t cvta_s(const void* p) {
    return (uint32_t)__cvta_generic_to_shared(p);
}

__device__ __forceinline__ uint2 cvt_h4(float4 v) {
    __half2 h0 = __floats2half2_rn(v.x, v.y);
    __half2 h1 = __floats2half2_rn(v.z, v.w);
    uint2 r; r.x = *(uint32_t*)&h0; r.y = *(uint32_t*)&h1; return r;
}

// fp16 hi/lo split (effective precision ~2^-22)
__device__ __forceinline__ void cvt_split4h(float4 v, uint2 &hi, uint2 &lo) {
    __half2 h0 = __floats2half2_rn(v.x, v.y);
    __half2 h1 = __floats2half2_rn(v.z, v.w);
    float rx = v.x - __half2float(h0.x);
    float ry = v.y - __half2float(h0.y);
    float rz = v.z - __half2float(h1.x);
    float rw = v.w - __half2float(h1.y);
    __half2 l0 = __floats2half2_rn(rx, ry);
    __half2 l1 = __floats2half2_rn(rz, rw);
    hi.x = *(uint32_t*)&h0; hi.y = *(uint32_t*)&h1;
    lo.x = *(uint32_t*)&l0; lo.y = *(uint32_t*)&l1;
}

// ===========================================================================
// FUSED attention kernel v4 (unchanged from round 8 — verified).
// ===========================================================================
#define QK_OFF   0
#define QK_PITCH 1040
#define E_OFF    33280
#define E_PITCH  1040
#define ES_OFF   99840
#define ES_PITCH 144
#define RED_OFF  104448
#define LP_OFF   104960
#define SMEM_FUSED 105984

__global__ __launch_bounds__(256, 2)
void fused_attn4(const __half* __restrict__ Qkh, const float* __restrict__ E,
                 const float* __restrict__ P, float* __restrict__ outA,
                 float* __restrict__ Gp, float* __restrict__ rows)
{
    extern __shared__ __align__(16) unsigned char sm[];
    const int sp = blockIdx.x;
    const int b  = blockIdx.y;
    const int tid  = threadIdx.x;
    const int lane = tid & 31;
    const int warp = tid >> 5;
    const int mw = warp >> 2;
    const int nw = warp & 3;

    const float*  Eb  = E   + (long)b*NPATCH*DIM;
    const __half* Qkb = Qkh + (long)b*KTOK*DIM;
    const float*  Pb  = P   + (long)b*NPATCH;
    float*        Ab  = outA + (long)b*KTOK*NPATCH;

    const int nbase = sp * (NPATCH/SPLITS);

    #pragma unroll
    for (int p = 0; p < 8; ++p) {
        int lin = tid + p*256;
        int r = lin >> 6, seg = lin & 63;
        uint4 v = *(const uint4*)(Qkb + r*DIM + seg*8);
        *(uint4*)(sm + QK_OFF + r*QK_PITCH + seg*16) = v;
    }
    {
        float pv = Pb[nbase + tid];
        ((float*)(sm + LP_OFF))[tid] = __logf(fminf(fmaxf(pv, 0.1f), 0.9f));
    }

    float accG[16][4];
    #pragma unroll
    for (int t2 = 0; t2 < 16; ++t2)
        #pragma unroll
        for (int r = 0; r < 4; ++r) accG[t2][r] = 0.f;
    float rsum0 = 0.f, rsum8 = 0.f;

    const uint32_t smb = cvta_s(sm);
    const uint32_t aQkBase = smb + QK_OFF + (mw*16 + (lane & 15))*QK_PITCH + (lane >> 4)*16;
    const uint32_t b1Base  = smb + E_OFF
        + (nw*16 + (lane & 7) + ((lane >> 4) & 1)*8)*E_PITCH + ((lane >> 3) & 1)*16;
    const uint32_t aEsBase = smb + ES_OFF + (mw*16 + (lane & 15))*ES_PITCH + (lane >> 4)*16;
    const uint32_t b2Base  = smb + E_OFF + (lane & 15)*E_PITCH + nw*256 + ((lane >> 4) & 1)*16;
    const float* LPs = (const float*)(sm + LP_OFF);

    for (int c = 0; c < 4; ++c) {
        const int n0 = nbase + c*64;
        __syncthreads();
        #pragma unroll 8
        for (int p = 0; p < 32; ++p) {
            int lin = tid + p*256;
            int r = lin >> 7, c4 = lin & 127;
            float4 v = *(const float4*)(Eb + (long)(n0 + r)*DIM + 4*c4);
            *(uint2*)(sm + E_OFF + r*E_PITCH + 8*c4) = cvt_h4(v);
        }
        __syncthreads();

        float sacc[2][4];
        #pragma unroll
        for (int j = 0; j < 2; ++j)
            #pragma unroll
            for (int r = 0; r < 4; ++r) sacc[j][r] = 0.f;
        #pragma unroll
        for (int ks = 0; ks < 32; ++ks) {
            uint32_t a[4], r0, r1, r2, r3;
            LDSM4(a[0],a[1],a[2],a[3], aQkBase + ks*32);
            LDSM4(r0,r1,r2,r3, b1Base + ks*32);
            MMA_F16(sacc[0], a, r0, r1);
            MMA_F16(sacc[1], a, r2, r3);
        }

        {
            const int mrow = mw*16 + (lane >> 2);
            #pragma unroll
            for (int j = 0; j < 2; ++j) {
                int nl = nw*16 + j*8 + 2*(lane & 3);
                int gn = n0 + nl;
                float lp0 = LPs[c*64 + nl];
                float lp1 = LPs[c*64 + nl + 1];
                float v0 = __expf(sacc[j][0]*SCALE_V + lp0);
                float v1 = __expf(sacc[j][1]*SCALE_V + lp1);
                float v2 = __expf(sacc[j][2]*SCALE_V + lp0);
                float v3 = __expf(sacc[j][3]*SCALE_V + lp1);
                rsum0 += v0 + v1; rsum8 += v2 + v3;
                *(float2*)(Ab + (long)mrow*NPATCH + gn)     = make_float2(v0, v1);
                *(float2*)(Ab + (long)(mrow+8)*NPATCH + gn) = make_float2(v2, v3);
                __half2 h01 = __floats2half2_rn(v0, v1);
                __half2 h23 = __floats2half2_rn(v2, v3);
                *(uint32_t*)(sm + ES_OFF + mrow*ES_PITCH + nl*2)     = *(uint32_t*)&h01;
                *(uint32_t*)(sm + ES_OFF + (mrow+8)*ES_PITCH + nl*2) = *(uint32_t*)&h23;
            }
        }
        __syncthreads();

        #pragma unroll
        for (int ks = 0; ks < 4; ++ks) {
            uint32_t a[4];
            LDSM4(a[0],a[1],a[2],a[3], aEsBase + ks*32);
            #pragma unroll
            for (int jt = 0; jt < 8; ++jt) {
                uint32_t r0, r1, r2, r3;
                LDSM4T(r0,r1,r2,r3, b2Base + ks*16*E_PITCH + jt*32);
                MMA_F16(accG[2*jt],   a, r0, r1);
                MMA_F16(accG[2*jt+1], a, r2, r3);
            }
        }
    }

    {
        float* Gpb = Gp + ((long)(b*SPLITS + sp)*KTOK)*DIM;
        const int mrow = mw*16 + (lane >> 2);
        #pragma unroll
        for (int t2 = 0; t2 < 16; ++t2) {
            int d = nw*128 + t2*8 + 2*(lane & 3);
            *(float2*)(Gpb + (long)mrow*DIM + d)     = make_float2(accG[t2][0], accG[t2][1]);
            *(float2*)(Gpb + (long)(mrow+8)*DIM + d) = make_float2(accG[t2][2], accG[t2][3]);
        }
    }

    rsum0 += __shfl_xor_sync(0xffffffffu, rsum0, 1);
    rsum0 += __shfl_xor_sync(0xffffffffu, rsum0, 2);
    rsum8 += __shfl_xor_sync(0xffffffffu, rsum8, 1);
    rsum8 += __shfl_xor_sync(0xffffffffu, rsum8, 2);
    {
        float (*srow)[4] = (float(*)[4])(sm + RED_OFF);
        __syncthreads();
        if ((lane & 3) == 0) {
            srow[mw*16 + (lane >> 2)][nw]     = rsum0;
            srow[mw*16 + 8 + (lane >> 2)][nw] = rsum8;
        }
        __syncthreads();
        if (tid < 32) {
            float s = srow[tid][0] + srow[tid][1] + srow[tid][2] + srow[tid][3];
            rows[(b*KTOK + tid)*SPLITS + sp] = s;
        }
    }
}

// ===========================================================================
// post kernel: blocks [0,256) reduce G partials; blocks [256,768) scale A rows.
// (unchanged from round 8 — verified, 8.5us)
// ===========================================================================
__global__ __launch_bounds__(256)
void post_kernel(const float* __restrict__ Gp, float* __restrict__ G,
                 const float* __restrict__ rows, float* __restrict__ A)
{
    if (blockIdx.x < 256) {
        int i = blockIdx.x*256 + threadIdx.x;
        int bb  = i >> 12;
        int rem = i & 4095;
        const float4* p = (const float4*)Gp + ((long)bb*SPLITS)*4096 + rem;
        float4 s = make_float4(0.f, 0.f, 0.f, 0.f);
        #pragma unroll
        for (int s2 = 0; s2 < SPLITS; ++s2) {
            float4 v = p[(long)s2*4096];
            s.x += v.x; s.y += v.y; s.z += v.z; s.w += v.w;
        }
        ((float4*)G)[i] = s;
    } else {
        int r = blockIdx.x - 256;
        float s = 0.f;
        #pragma unroll
        for (int c = 0; c < SPLITS; ++c) s += rows[r*SPLITS + c];
        float inv = 1.f / s;
        float4* pa = (float4*)(A + (long)r*NPATCH);
        #pragma unroll
        for (int q = 0; q < 4; ++q) {
            int idx = threadIdx.x + q*256;
            float4 v = pa[idx];
            v.x *= inv; v.y *= inv; v.z *= inv; v.w *= inv;
            pa[idx] = v;
        }
    }
}

// ===========================================================================
// proj_qk (unchanged from round 8 — verified).
// ===========================================================================
#define PJ_T     0
#define PJ_W     2560
#define PJ_Q     23040
#define PJ_BYTES 39936
#define QS_PITCH 528

__global__ __launch_bounds__(256)
void proj_qk(const float* __restrict__ T, const float* __restrict__ Wq,
             const float* __restrict__ Wk, __half* __restrict__ Qkh)
{
    __shared__ __align__(16) unsigned char sm[PJ_BYTES];
    const int nb = blockIdx.x;
    const int b  = blockIdx.y;
    const int tid  = threadIdx.x;
    const int lane = tid & 31;
    const int warp = tid >> 5;
    const int mw = warp >> 2;
    const int nw = warp & 3;

    const float* Tb = T + (long)b*KTOK*DIM;

    float accQ[8][4];
    #pragma unroll
    for (int j = 0; j < 8; ++j)
        #pragma unroll
        for (int r = 0; r < 4; ++r) accQ[j][r] = 0.f;

    const uint32_t aT = cvta_s(sm + PJ_T)
        + (mw*16 + (lane & 15))*80 + (lane >> 4)*16;
    uint32_t bW[4];
    #pragma unroll
    for (int jj = 0; jj < 4; ++jj)
        bW[jj] = cvta_s(sm + PJ_W)
            + (nw*64 + jj*16 + (lane & 7) + ((lane >> 4) & 1)*8)*80
            + ((lane >> 3) & 1)*16;

    const int am = tid >> 3, ak4 = tid & 7;

    float4 pt, pw[8];
    pt = *(const float4*)(Tb + am*DIM + 4*ak4);
    #pragma unroll
    for (int p = 0; p < 8; ++p) {
        int lin = tid + p*256;
        pw[p] = *(const float4*)(Wq + (long)(lin >> 3)*DIM + 4*(lin & 7));
    }

    for (int k0 = 0; k0 < DIM; k0 += 32) {
        *(uint2*)(sm + PJ_T + am*80 + 8*ak4) = cvt_h4(pt);
        #pragma unroll
        for (int p = 0; p < 8; ++p) {
            int lin = tid + p*256;
            *(uint2*)(sm + PJ_W + (lin >> 3)*80 + 8*(lin & 7)) = cvt_h4(pw[p]);
        }
        __syncthreads();

        int kn = k0 + 32;
        if (kn < DIM) {
            pt = *(const float4*)(Tb + am*DIM + kn + 4*ak4);
            #pragma unroll
            for (int p = 0; p < 8; ++p) {
                int lin = tid + p*256;
                pw[p] = *(const float4*)(Wq + (long)(lin >> 3)*DIM + kn + 4*(lin & 7));
            }
        }

        #pragma unroll
        for (int kt = 0; kt < 2; ++kt) {
            uint32_t a[4];
            LDSM4(a[0],a[1],a[2],a[3], aT + kt*32);
            #pragma unroll
            for (int jj = 0; jj < 4; ++jj) {
                uint32_t r0,r1,r2,r3;
                LDSM4(r0,r1,r2,r3, bW[jj] + kt*32);
                MMA_F16(accQ[2*jj],   a, r0, r1);
                MMA_F16(accQ[2*jj+1], a, r2, r3);
            }
        }
        __syncthreads();
    }

    const int mrow = mw*16 + (lane >> 2);
    #pragma unroll
    for (int j = 0; j < 8; ++j) {
        int col = nw*64 + j*8 + 2*(lane & 3);
        __half2 h01 = __floats2half2_rn(accQ[j][0], accQ[j][1]);
        __half2 h23 = __floats2half2_rn(accQ[j][2], accQ[j][3]);
        *(uint32_t*)(sm + PJ_Q + mrow*QS_PITCH + col*2)     = *(uint32_t*)&h01;
        *(uint32_t*)(sm + PJ_Q + (mrow+8)*QS_PITCH + col*2) = *(uint32_t*)&h23;
    }
    __syncthreads();

    float accK[4][4];
    #pragma unroll
    for (int j = 0; j < 4; ++j)
        #pragma unroll
        for (int r = 0; r < 4; ++r) accK[j][r] = 0.f;

    const uint32_t aQ = cvta_s(sm + PJ_Q)
        + (mw*16 + (lane & 15))*QS_PITCH + (lane >> 4)*16;
    uint32_t bK[2];
    #pragma unroll
    for (int jj = 0; jj < 2; ++jj)
        bK[jj] = cvta_s(sm + PJ_W) + (lane & 15)*272
            + (nw*32 + jj*16)*2 + ((lane >> 4) & 1)*16;

    const int n0 = nb*128;
    float4 pk[4];
    #pragma unroll
    for (int p = 0; p < 4; ++p) {
        int lin = tid + p*256;
        pk[p] = *(const float4*)(Wk + (long)(lin >> 5)*DIM + n0 + 4*(lin & 31));
    }

    for (int k0 = 0; k0 < DHEAD; k0 += 32) {
        #pragma unroll
        for (int p = 0; p < 4; ++p) {
            int lin = tid + p*256;
            *(uint2*)(sm + PJ_W + (lin >> 5)*272 + 8*(lin & 31)) = cvt_h4(pk[p]);
        }
        __syncthreads();

        int kn = k0 + 32;
        if (kn < DHEAD) {
            #pragma unroll
            for (int p = 0; p < 4; ++p) {
                int lin = tid + p*256;
                pk[p] = *(const float4*)(Wk + (long)(kn + (lin >> 5))*DIM + n0 + 4*(lin & 31));
            }
        }

        #pragma unroll
        for (int kt = 0; kt < 2; ++kt) {
            uint32_t a[4];
            LDSM4(a[0],a[1],a[2],a[3], aQ + k0*2 + kt*32);
            #pragma unroll
            for (int jj = 0; jj < 2; ++jj) {
                uint32_t r0,r1,r2,r3;
                LDSM4T(r0,r1,r2,r3, bK[jj] + kt*16*272);
                MMA_F16(accK[2*jj],   a, r0, r1);
                MMA_F16(accK[2*jj+1], a, r2, r3);
            }
        }
        __syncthreads();
    }

    __half* out = Qkh + (long)b*KTOK*DIM;
    #pragma unroll
    for (int j = 0; j < 4; ++j) {
        int n = n0 + nw*32 + j*8 + 2*(lane & 3);
        __half2 h01 = __floats2half2_rn(accK[j][0], accK[j][1]);
        __half2 h23 = __floats2half2_rn(accK[j][2], accK[j][3]);
        *(uint32_t*)(out + (long)mrow*DIM + n)     = *(uint32_t*)&h01;
        *(uint32_t*)(out + (long)(mrow+8)*DIM + n) = *(uint32_t*)&h23;
    }
}

// ===========================================================================
// tail_fused: per batch b (16 blocks, 256 thr):
//   phase1: F[32,256] = G[32,512] @ Wv^T   (fp16 hi/lo, 3-MMA; Wv prefetched)
//   phase2: out[32,512] = F @ Wo^T in two n-halves -> smem fp32
//   phase3: L2-normalize rows in smem -> gmem
// ===========================================================================
#define T_GH   0              // G hi: 32 x 1040
#define T_GL   33280          // G lo
#define T_OUT  0              // phase2: out fp32, 32 x 2064 (reuses G area)
#define OUT_PITCH 2064
#define T_WH   66560          // weight stage hi: 256 x 80
#define T_WL   87040          // weight stage lo
#define T_FH   107520         // F hi: 32 x 528
#define T_FL   124416         // F lo
#define T_BYTES 141312

__global__ __launch_bounds__(256)
void tail_fused(const float* __restrict__ G, const float* __restrict__ Wv,
                const float* __restrict__ Wo, float* __restrict__ outF)
{
    extern __shared__ __align__(16) unsigned char sm[];
    const int b = blockIdx.x;
    const int tid  = threadIdx.x;
    const int lane = tid & 31;
    const int warp = tid >> 5;
    const int mw = warp >> 2;
    const int nw = warp & 3;

    const uint32_t smb = cvta_s(sm);
    const float* Gb = G + (long)b*KTOK*DIM;

    // ---- stage G[32,512] -> fp16 hi/lo planes ----
    #pragma unroll
    for (int p = 0; p < 16; ++p) {
        int lin = tid + p*256;
        int r = lin >> 7, c4 = lin & 127;
        float4 v = *(const float4*)(Gb + r*DIM + 4*c4);
        uint2 hi, lo; cvt_split4h(v, hi, lo);
        *(uint2*)(sm + T_GH + r*1040 + 8*c4) = hi;
        *(uint2*)(sm + T_GL + r*1040 + 8*c4) = lo;
    }

    // ldmatrix addresses
    const uint32_t aGH = smb + T_GH + (mw*16 + (lane & 15))*1040 + (lane >> 4)*16;
    const uint32_t aGL = aGH + (T_GL - T_GH);
    const uint32_t aFH = smb + T_FH + (mw*16 + (lane & 15))*528 + (lane >> 4)*16;
    const uint32_t aFL = aFH + (T_FL - T_FH);
    uint32_t bWH[4];
    #pragma unroll
    for (int jj = 0; jj < 4; ++jj)
        bWH[jj] = smb + T_WH
            + (nw*64 + jj*16 + (lane & 7) + ((lane >> 4) & 1)*8)*80
            + ((lane >> 3) & 1)*16;

    // ---------- Phase 1: F = G @ Wv^T ----------
    float accF[8][4];
    #pragma unroll
    for (int j = 0; j < 8; ++j)
        #pragma unroll
        for (int r = 0; r < 4; ++r) accF[j][r] = 0.f;

    float4 pw[8];
    #pragma unroll
    for (int p = 0; p < 8; ++p) {
        int lin = tid + p*256;
        pw[p] = *(const float4*)(Wv + (long)(lin >> 3)*DIM + 4*(lin & 7));
    }
    __syncthreads();   // G planes visible

    for (int step = 0; step < 16; ++step) {
        #pragma unroll
        for (int p = 0; p < 8; ++p) {
            int lin = tid + p*256;
            uint2 hi, lo; cvt_split4h(pw[p], hi, lo);
            *(uint2*)(sm + T_WH + (lin >> 3)*80 + 8*(lin & 7)) = hi;
            *(uint2*)(sm + T_WL + (lin >> 3)*80 + 8*(lin & 7)) = lo;
        }
        __syncthreads();

        if (step < 15) {
            int kn = (step + 1) * 32;
            #pragma unroll
            for (int p = 0; p < 8; ++p) {
                int lin = tid + p*256;
                pw[p] = *(const float4*)(Wv + (long)(lin >> 3)*DIM + kn + 4*(lin & 7));
            }
        }

        #pragma unroll
        for (int kt = 0; kt < 2; ++kt) {
            uint32_t ah[4], al[4];
            LDSM4(ah[0],ah[1],ah[2],ah[3], aGH + step*64 + kt*32);
            LDSM4(al[0],al[1],al[2],al[3], aGL + step*64 + kt*32);
            uint32_t bh[8][2], bl[8][2];
            #pragma unroll
            for (int jj = 0; jj < 4; ++jj) {
                uint32_t r0,r1,r2,r3;
                LDSM4(r0,r1,r2,r3, bWH[jj] + kt*32);
                bh[2*jj][0]=r0; bh[2*jj][1]=r1; bh[2*jj+1][0]=r2; bh[2*jj+1][1]=r3;
                LDSM4(r0,r1,r2,r3, bWH[jj] + (T_WL - T_WH) + kt*32);
                bl[2*jj][0]=r0; bl[2*jj][1]=r1; bl[2*jj+1][0]=r2; bl[2*jj+1][1]=r3;
            }
            #pragma unroll
            for (int j = 0; j < 8; ++j) {
                MMA_F16(accF[j], ah, bh[j][0], bh[j][1]);
                MMA_F16(accF[j], ah, bl[j][0], bl[j][1]);
                MMA_F16(accF[j], al, bh[j][0], bh[j][1]);
            }
        }
        __syncthreads();
    }

    // ---- write F -> fp16 hi/lo smem planes ----
    const int mrow = mw*16 + (lane >> 2);
    #pragma unroll
    for (int j = 0; j < 8; ++j) {
        int col = nw*64 + j*8 + 2*(lane & 3);
        float v0 = accF[j][0], v1 = accF[j][1], v2 = accF[j][2], v3 = accF[j][3];
        __half2 h01 = __floats2half2_rn(v0, v1);
        __half2 l01 = __floats2half2_rn(v0 - __half2float(h01.x), v1 - __half2float(h01.y));
        __half2 h23 = __floats2half2_rn(v2, v3);
        __half2 l23 = __floats2half2_rn(v2 - __half2float(h23.x), v3 - __half2float(h23.y));
        *(uint32_t*)(sm + T_FH + mrow*528 + col*2)     = *(uint32_t*)&h01;
        *(uint32_t*)(sm + T_FL + mrow*528 + col*2)     = *(uint32_t*)&l01;
        *(uint32_t*)(sm + T_FH + (mrow+8)*528 + col*2) = *(uint32_t*)&h23;
        *(uint32_t*)(sm + T_FL + (mrow+8)*528 + col*2) = *(uint32_t*)&l23;
    }

    // prefetch Wo half 0, step 0
    #pragma unroll
    for (int p = 0; p < 8; ++p) {
        int lin = tid + p*256;
        pw[p] = *(const float4*)(Wo + (long)(lin >> 3)*DHEAD + 4*(lin & 7));
    }

    // ---------- Phase 2: out = F @ Wo^T (two n-halves) ----------
    for (int h = 0; h < 2; ++h) {
        float accO[8][4];
        #pragma unroll
        for (int j = 0; j < 8; ++j)
            #pragma unroll
            for (int r = 0; r < 4; ++r) accO[j][r] = 0.f;

        for (int step = 0; step < 8; ++step) {
            #pragma unroll
            for (int p = 0; p < 8; ++p) {
                int lin = tid + p*256;
                uint2 hi, lo; cvt_split4h(pw[p], hi, lo);
                *(uint2*)(sm + T_WH + (lin >> 3)*80 + 8*(lin & 7)) = hi;
                *(uint2*)(sm + T_WL + (lin >> 3)*80 + 8*(lin & 7)) = lo;
            }
            __syncthreads();   // also covers F visibility on first iteration

            // prefetch next tile
            if (step < 7 || h == 0) {
                int nh = (step < 7) ? h : 1;
                int kn = (step < 7) ? (step + 1)*32 : 0;
                #pragma unroll
                for (int p = 0; p < 8; ++p) {
                    int lin = tid + p*256;
                    pw[p] = *(const float4*)(Wo + (long)(nh*256 + (lin >> 3))*DHEAD + kn + 4*(lin & 7));
                }
            }

            #pragma unroll
            for (int kt = 0; kt < 2; ++kt) {
                uint32_t ah[4], al[4];
                LDSM4(ah[0],ah[1],ah[2],ah[3], aFH + step*64 + kt*32);
                LDSM4(al[0],al[1],al[2],al[3], aFL + step*64 + kt*32);
                uint32_t bh[8][2], bl[8][2];
                #pragma unroll
                for (int jj = 0; jj < 4; ++jj) {
                    uint32_t r0,r1,r2,r3;
                    LDSM4(r0,r1,r2,r3, bWH[jj] + kt*32);
                    bh[2*jj][0]=r0; bh[2*jj][1]=r1; bh[2*jj+1][0]=r2; bh[2*jj+1][1]=r3;
                    LDSM4(r0,r1,r2,r3, bWH[jj] + (T_WL - T_WH) + kt*32);
                    bl[2*jj][0]=r0; bl[2*jj][1]=r1; bl[2*jj+1][0]=r2; bl[2*jj+1][1]=r3;
                }
                #pragma unroll
                for (int j = 0; j < 8; ++j) {
                    MMA_F16(accO[j], ah, bh[j][0], bh[j][1]);
                    MMA_F16(accO[j], ah, bl[j][0], bl[j][1]);
                    MMA_F16(accO[j], al, bh[j][0], bh[j][1]);
                }
            }
            __syncthreads();
        }

        // epilogue: out half -> smem fp32
        #pragma unroll
        for (int j = 0; j < 8; ++j) {
            int col = h*256 + nw*64 + j*8 + 2*(lane & 3);
            *(float2*)(sm + T_OUT + mrow*OUT_PITCH + col*4)
                = make_float2(accO[j][0], accO[j][1]);
            *(float2*)(sm + T_OUT + (mrow+8)*OUT_PITCH + col*4)
                = make_float2(accO[j][2], accO[j][3]);
        }
    }
    __syncthreads();

    // ---------- Phase 3: L2-normalize rows, write gmem ----------
    {
        int r = tid >> 3;          // 0..31
        int q = tid & 7;           // 0..7
        const float* orow = (const float*)(sm + T_OUT + r*OUT_PITCH);
        float4 vv[16];
        float ss = 0.f;
        #pragma unroll
        for (int i = 0; i < 16; ++i) {
            vv[i] = *(const float4*)(orow + q*64 + i*4);
            ss += vv[i].x*vv[i].x + vv[i].y*vv[i].y + vv[i].z*vv[i].z + vv[i].w*vv[i].w;
        }
        ss += __shfl_xor_sync(0xffffffffu, ss, 1);
        ss += __shfl_xor_sync(0xffffffffu, ss, 2);
        ss += __shfl_xor_sync(0xffffffffu, ss, 4);
        float inv = 1.f / (sqrtf(ss) + 1e-8f);
        float* dst = outF + ((long)b*KTOK + r)*DIM + q*64;
        #pragma unroll
        for (int i = 0; i < 16; ++i) {
            float4 v = vv[i];
            v.x *= inv; v.y *= inv; v.z *= inv; v.w *= inv;
            *(float4*)(dst + i*4) = v;
        }
    }
}

extern "C" void kernel_launch(void* const* d_in, const int* in_sizes, int n_in,
                              void* d_out, int out_size)
{
    const float* E  = (const float*)d_in[0];
    const float* T  = (const float*)d_in[1];
    const float* P  = (const float*)d_in[2];
    const float* Wq = (const float*)d_in[3];
    const float* Wk = (const float*)d_in[4];
    const float* Wv = (const float*)d_in[5];
    const float* Wo = (const float*)d_in[6];

    float* outF = (float*)d_out;
    float* outA = (float*)d_out + (long)BATCH*KTOK*DIM;

    float *pGp, *pG, *pRows;
    __half* pQkh;
    cudaGetSymbolAddress((void**)&pQkh,  g_Qkh);
    cudaGetSymbolAddress((void**)&pGp,   g_Gp);
    cudaGetSymbolAddress((void**)&pG,    g_G);
    cudaGetSymbolAddress((void**)&pRows, g_rows);

    cudaFuncSetAttribute(fused_attn4,
        cudaFuncAttributeMaxDynamicSharedMemorySize, SMEM_FUSED);
    cudaFuncSetAttribute(tail_fused,
        cudaFuncAttributeMaxDynamicSharedMemorySize, T_BYTES);

    dim3 blk(256);

    // 1) Qk = (T @ Wq^T) @ Wk  (merged, fp16 out)
    proj_qk<<<dim3(4, BATCH), blk>>>(T, Wq, Wk, pQkh);

    // 2) FUSED: expS/A(unnorm) + row-sum partials + G partials
    fused_attn4<<<dim3(SPLITS, BATCH), blk, SMEM_FUSED>>>(
        pQkh, E, P, outA, pGp, pRows);

    // 3) post: G reduce (256 blocks) + A row-scale (512 blocks)
    post_kernel<<<768, blk>>>(pGp, pG, pRows, outA);

    // 4) tail: F = G@Wv^T; out = F@Wo^T; normalize — one kernel
    tail_fused<<<BATCH, blk, T_BYTES>>>(pG, Wv, Wo, outF);
}

// round 10
// speedup vs baseline: 1.1351x; 1.1351x over previous
#include <cuda_runtime.h>
#include <cuda_bf16.h>
#include <cuda_fp16.h>
#include <math.h>
#include <stdint.h>

// Problem constants
#define BATCH 16
#define NPATCH 4096
#define KTOK 32
#define DIM 512
#define DHEAD 256
#define SCALE_V 0.0625f   // 256^-0.5

#define SPLITS 16

// Scratch (no allocation allowed -> device globals)
__device__ __half g_Qkh [BATCH*KTOK*DIM];
__device__ float  g_Gp  [SPLITS*BATCH*KTOK*DIM];
__device__ float  g_G   [BATCH*KTOK*DIM];
__device__ float  g_F   [BATCH*KTOK*DHEAD];
__device__ float  g_rows[BATCH*KTOK*SPLITS];

// ---------------------------------------------------------------------------

#define LDSM4(R0,R1,R2,R3,ADDR) \
    asm volatile("ldmatrix.sync.aligned.m8n8.x4.shared.b16 {%0,%1,%2,%3}, [%4];" \
        : "=r"(R0),"=r"(R1),"=r"(R2),"=r"(R3) : "r"(ADDR))

#define LDSM4T(R0,R1,R2,R3,ADDR) \
    asm volatile("ldmatrix.sync.aligned.m8n8.x4.trans.shared.b16 {%0,%1,%2,%3}, [%4];" \
        : "=r"(R0),"=r"(R1),"=r"(R2),"=r"(R3) : "r"(ADDR))

#define MMA_F16(C,A,B0,B1) \
    asm volatile("mma.sync.aligned.m16n8k16.row.col.f32.f16.f16.f32 " \
        "{%0,%1,%2,%3},{%4,%5,%6,%7},{%8,%9},{%0,%1,%2,%3};" \
        : "+f"((C)[0]),"+f"((C)[1]),"+f"((C)[2]),"+f"((C)[3]) \
        : "r"((A)[0]),"r"((A)[1]),"r"((A)[2]),"r"((A)[3]),"r"(B0),"r"(B1))

__device__ __forceinline__ uint32_t cvta_s(const void* p) {
    return (uint32_t)__cvta_generic_to_shared(p);
}

__device__ __forceinline__ uint2 cvt_h4(float4 v) {
    __half2 h0 = __floats2half2_rn(v.x, v.y);
    __half2 h1 = __floats2half2_rn(v.z, v.w);
    uint2 r; r.x = *(uint32_t*)&h0; r.y = *(uint32_t*)&h1; return r;
}

// fp16 hi/lo split (effective precision ~2^-22)
__device__ __forceinline__ void cvt_split4h(float4 v, uint2 &hi, uint2 &lo) {
    __half2 h0 = __floats2half2_rn(v.x, v.y);
    __half2 h1 = __floats2half2_rn(v.z, v.w);
    float rx = v.x - __half2float(h0.x);
    float ry = v.y - __half2float(h0.y);
    float rz = v.z - __half2float(h1.x);
    float rw = v.w - __half2float(h1.y);
    __half2 l0 = __floats2half2_rn(rx, ry);
    __half2 l1 = __floats2half2_rn(rz, rw);
    hi.x = *(uint32_t*)&h0; hi.y = *(uint32_t*)&h1;
    lo.x = *(uint32_t*)&l0; lo.y = *(uint32_t*)&l1;
}

// ===========================================================================
// FUSED attention kernel v4 (unchanged — verified).
// ===========================================================================
#define QK_OFF   0
#define QK_PITCH 1040
#define E_OFF    33280
#define E_PITCH  1040
#define ES_OFF   99840
#define ES_PITCH 144
#define RED_OFF  104448
#define LP_OFF   104960
#define SMEM_FUSED 105984

__global__ __launch_bounds__(256, 2)
void fused_attn4(const __half* __restrict__ Qkh, const float* __restrict__ E,
                 const float* __restrict__ P, float* __restrict__ outA,
                 float* __restrict__ Gp, float* __restrict__ rows)
{
    extern __shared__ __align__(16) unsigned char sm[];
    const int sp = blockIdx.x;
    const int b  = blockIdx.y;
    const int tid  = threadIdx.x;
    const int lane = tid & 31;
    const int warp = tid >> 5;
    const int mw = warp >> 2;
    const int nw = warp & 3;

    const float*  Eb  = E   + (long)b*NPATCH*DIM;
    const __half* Qkb = Qkh + (long)b*KTOK*DIM;
    const float*  Pb  = P   + (long)b*NPATCH;
    float*        Ab  = outA + (long)b*KTOK*NPATCH;

    const int nbase = sp * (NPATCH/SPLITS);

    #pragma unroll
    for (int p = 0; p < 8; ++p) {
        int lin = tid + p*256;
        int r = lin >> 6, seg = lin & 63;
        uint4 v = *(const uint4*)(Qkb + r*DIM + seg*8);
        *(uint4*)(sm + QK_OFF + r*QK_PITCH + seg*16) = v;
    }
    {
        float pv = Pb[nbase + tid];
        ((float*)(sm + LP_OFF))[tid] = __logf(fminf(fmaxf(pv, 0.1f), 0.9f));
    }

    float accG[16][4];
    #pragma unroll
    for (int t2 = 0; t2 < 16; ++t2)
        #pragma unroll
        for (int r = 0; r < 4; ++r) accG[t2][r] = 0.f;
    float rsum0 = 0.f, rsum8 = 0.f;

    const uint32_t smb = cvta_s(sm);
    const uint32_t aQkBase = smb + QK_OFF + (mw*16 + (lane & 15))*QK_PITCH + (lane >> 4)*16;
    const uint32_t b1Base  = smb + E_OFF
        + (nw*16 + (lane & 7) + ((lane >> 4) & 1)*8)*E_PITCH + ((lane >> 3) & 1)*16;
    const uint32_t aEsBase = smb + ES_OFF + (mw*16 + (lane & 15))*ES_PITCH + (lane >> 4)*16;
    const uint32_t b2Base  = smb + E_OFF + (lane & 15)*E_PITCH + nw*256 + ((lane >> 4) & 1)*16;
    const float* LPs = (const float*)(sm + LP_OFF);

    for (int c = 0; c < 4; ++c) {
        const int n0 = nbase + c*64;
        __syncthreads();
        #pragma unroll 8
        for (int p = 0; p < 32; ++p) {
            int lin = tid + p*256;
            int r = lin >> 7, c4 = lin & 127;
            float4 v = *(const float4*)(Eb + (long)(n0 + r)*DIM + 4*c4);
            *(uint2*)(sm + E_OFF + r*E_PITCH + 8*c4) = cvt_h4(v);
        }
        __syncthreads();

        float sacc[2][4];
        #pragma unroll
        for (int j = 0; j < 2; ++j)
            #pragma unroll
            for (int r = 0; r < 4; ++r) sacc[j][r] = 0.f;
        #pragma unroll
        for (int ks = 0; ks < 32; ++ks) {
            uint32_t a[4], r0, r1, r2, r3;
            LDSM4(a[0],a[1],a[2],a[3], aQkBase + ks*32);
            LDSM4(r0,r1,r2,r3, b1Base + ks*32);
            MMA_F16(sacc[0], a, r0, r1);
            MMA_F16(sacc[1], a, r2, r3);
        }

        {
            const int mrow = mw*16 + (lane >> 2);
            #pragma unroll
            for (int j = 0; j < 2; ++j) {
                int nl = nw*16 + j*8 + 2*(lane & 3);
                int gn = n0 + nl;
                float lp0 = LPs[c*64 + nl];
                float lp1 = LPs[c*64 + nl + 1];
                float v0 = __expf(sacc[j][0]*SCALE_V + lp0);
                float v1 = __expf(sacc[j][1]*SCALE_V + lp1);
                float v2 = __expf(sacc[j][2]*SCALE_V + lp0);
                float v3 = __expf(sacc[j][3]*SCALE_V + lp1);
                rsum0 += v0 + v1; rsum8 += v2 + v3;
                *(float2*)(Ab + (long)mrow*NPATCH + gn)     = make_float2(v0, v1);
                *(float2*)(Ab + (long)(mrow+8)*NPATCH + gn) = make_float2(v2, v3);
                __half2 h01 = __floats2half2_rn(v0, v1);
                __half2 h23 = __floats2half2_rn(v2, v3);
                *(uint32_t*)(sm + ES_OFF + mrow*ES_PITCH + nl*2)     = *(uint32_t*)&h01;
                *(uint32_t*)(sm + ES_OFF + (mrow+8)*ES_PITCH + nl*2) = *(uint32_t*)&h23;
            }
        }
        __syncthreads();

        #pragma unroll
        for (int ks = 0; ks < 4; ++ks) {
            uint32_t a[4];
            LDSM4(a[0],a[1],a[2],a[3], aEsBase + ks*32);
            #pragma unroll
            for (int jt = 0; jt < 8; ++jt) {
                uint32_t r0, r1, r2, r3;
                LDSM4T(r0,r1,r2,r3, b2Base + ks*16*E_PITCH + jt*32);
                MMA_F16(accG[2*jt],   a, r0, r1);
                MMA_F16(accG[2*jt+1], a, r2, r3);
            }
        }
    }

    {
        float* Gpb = Gp + ((long)(b*SPLITS + sp)*KTOK)*DIM;
        const int mrow = mw*16 + (lane >> 2);
        #pragma unroll
        for (int t2 = 0; t2 < 16; ++t2) {
            int d = nw*128 + t2*8 + 2*(lane & 3);
            *(float2*)(Gpb + (long)mrow*DIM + d)     = make_float2(accG[t2][0], accG[t2][1]);
            *(float2*)(Gpb + (long)(mrow+8)*DIM + d) = make_float2(accG[t2][2], accG[t2][3]);
        }
    }

    rsum0 += __shfl_xor_sync(0xffffffffu, rsum0, 1);
    rsum0 += __shfl_xor_sync(0xffffffffu, rsum0, 2);
    rsum8 += __shfl_xor_sync(0xffffffffu, rsum8, 1);
    rsum8 += __shfl_xor_sync(0xffffffffu, rsum8, 2);
    {
        float (*srow)[4] = (float(*)[4])(sm + RED_OFF);
        __syncthreads();
        if ((lane & 3) == 0) {
            srow[mw*16 + (lane >> 2)][nw]     = rsum0;
            srow[mw*16 + 8 + (lane >> 2)][nw] = rsum8;
        }
        __syncthreads();
        if (tid < 32) {
            float s = srow[tid][0] + srow[tid][1] + srow[tid][2] + srow[tid][3];
            rows[(b*KTOK + tid)*SPLITS + sp] = s;
        }
    }
}

// ===========================================================================
// post kernel: blocks [0,256) reduce G partials; blocks [256,768) scale A rows.
// ===========================================================================
__global__ __launch_bounds__(256)
void post_kernel(const float* __restrict__ Gp, float* __restrict__ G,
                 const float* __restrict__ rows, float* __restrict__ A)
{
    if (blockIdx.x < 256) {
        int i = blockIdx.x*256 + threadIdx.x;
        int bb  = i >> 12;
        int rem = i & 4095;
        const float4* p = (const float4*)Gp + ((long)bb*SPLITS)*4096 + rem;
        float4 s = make_float4(0.f, 0.f, 0.f, 0.f);
        #pragma unroll
        for (int s2 = 0; s2 < SPLITS; ++s2) {
            float4 v = p[(long)s2*4096];
            s.x += v.x; s.y += v.y; s.z += v.z; s.w += v.w;
        }
        ((float4*)G)[i] = s;
    } else {
        int r = blockIdx.x - 256;
        float s = 0.f;
        #pragma unroll
        for (int c = 0; c < SPLITS; ++c) s += rows[r*SPLITS + c];
        float inv = 1.f / s;
        float4* pa = (float4*)(A + (long)r*NPATCH);
        #pragma unroll
        for (int q = 0; q < 4; ++q) {
            int idx = threadIdx.x + q*256;
            float4 v = pa[idx];
            v.x *= inv; v.y *= inv; v.z *= inv; v.w *= inv;
            pa[idx] = v;
        }
    }
}

// ===========================================================================
// proj_qk (unchanged — verified).
// ===========================================================================
#define PJ_T     0
#define PJ_W     2560
#define PJ_Q     23040
#define PJ_BYTES 39936
#define QS_PITCH 528

__global__ __launch_bounds__(256)
void proj_qk(const float* __restrict__ T, const float* __restrict__ Wq,
             const float* __restrict__ Wk, __half* __restrict__ Qkh)
{
    __shared__ __align__(16) unsigned char sm[PJ_BYTES];
    const int nb = blockIdx.x;
    const int b  = blockIdx.y;
    const int tid  = threadIdx.x;
    const int lane = tid & 31;
    const int warp = tid >> 5;
    const int mw = warp >> 2;
    const int nw = warp & 3;

    const float* Tb = T + (long)b*KTOK*DIM;

    float accQ[8][4];
    #pragma unroll
    for (int j = 0; j < 8; ++j)
        #pragma unroll
        for (int r = 0; r < 4; ++r) accQ[j][r] = 0.f;

    const uint32_t aT = cvta_s(sm + PJ_T)
        + (mw*16 + (lane & 15))*80 + (lane >> 4)*16;
    uint32_t bW[4];
    #pragma unroll
    for (int jj = 0; jj < 4; ++jj)
        bW[jj] = cvta_s(sm + PJ_W)
            + (nw*64 + jj*16 + (lane & 7) + ((lane >> 4) & 1)*8)*80
            + ((lane >> 3) & 1)*16;

    const int am = tid >> 3, ak4 = tid & 7;

    float4 pt, pw[8];
    pt = *(const float4*)(Tb + am*DIM + 4*ak4);
    #pragma unroll
    for (int p = 0; p < 8; ++p) {
        int lin = tid + p*256;
        pw[p] = *(const float4*)(Wq + (long)(lin >> 3)*DIM + 4*(lin & 7));
    }

    for (int k0 = 0; k0 < DIM; k0 += 32) {
        *(uint2*)(sm + PJ_T + am*80 + 8*ak4) = cvt_h4(pt);
        #pragma unroll
        for (int p = 0; p < 8; ++p) {
            int lin = tid + p*256;
            *(uint2*)(sm + PJ_W + (lin >> 3)*80 + 8*(lin & 7)) = cvt_h4(pw[p]);
        }
        __syncthreads();

        int kn = k0 + 32;
        if (kn < DIM) {
            pt = *(const float4*)(Tb + am*DIM + kn + 4*ak4);
            #pragma unroll
            for (int p = 0; p < 8; ++p) {
                int lin = tid + p*256;
                pw[p] = *(const float4*)(Wq + (long)(lin >> 3)*DIM + kn + 4*(lin & 7));
            }
        }

        #pragma unroll
        for (int kt = 0; kt < 2; ++kt) {
            uint32_t a[4];
            LDSM4(a[0],a[1],a[2],a[3], aT + kt*32);
            #pragma unroll
            for (int jj = 0; jj < 4; ++jj) {
                uint32_t r0,r1,r2,r3;
                LDSM4(r0,r1,r2,r3, bW[jj] + kt*32);
                MMA_F16(accQ[2*jj],   a, r0, r1);
                MMA_F16(accQ[2*jj+1], a, r2, r3);
            }
        }
        __syncthreads();
    }

    const int mrow = mw*16 + (lane >> 2);
    #pragma unroll
    for (int j = 0; j < 8; ++j) {
        int col = nw*64 + j*8 + 2*(lane & 3);
        __half2 h01 = __floats2half2_rn(accQ[j][0], accQ[j][1]);
        __half2 h23 = __floats2half2_rn(accQ[j][2], accQ[j][3]);
        *(uint32_t*)(sm + PJ_Q + mrow*QS_PITCH + col*2)     = *(uint32_t*)&h01;
        *(uint32_t*)(sm + PJ_Q + (mrow+8)*QS_PITCH + col*2) = *(uint32_t*)&h23;
    }
    __syncthreads();

    float accK[4][4];
    #pragma unroll
    for (int j = 0; j < 4; ++j)
        #pragma unroll
        for (int r = 0; r < 4; ++r) accK[j][r] = 0.f;

    const uint32_t aQ = cvta_s(sm + PJ_Q)
        + (mw*16 + (lane & 15))*QS_PITCH + (lane >> 4)*16;
    uint32_t bK[2];
    #pragma unroll
    for (int jj = 0; jj < 2; ++jj)
        bK[jj] = cvta_s(sm + PJ_W) + (lane & 15)*272
            + (nw*32 + jj*16)*2 + ((lane >> 4) & 1)*16;

    const int n0 = nb*128;
    float4 pk[4];
    #pragma unroll
    for (int p = 0; p < 4; ++p) {
        int lin = tid + p*256;
        pk[p] = *(const float4*)(Wk + (long)(lin >> 5)*DIM + n0 + 4*(lin & 31));
    }

    for (int k0 = 0; k0 < DHEAD; k0 += 32) {
        #pragma unroll
        for (int p = 0; p < 4; ++p) {
            int lin = tid + p*256;
            *(uint2*)(sm + PJ_W + (lin >> 5)*272 + 8*(lin & 31)) = cvt_h4(pk[p]);
        }
        __syncthreads();

        int kn = k0 + 32;
        if (kn < DHEAD) {
            #pragma unroll
            for (int p = 0; p < 4; ++p) {
                int lin = tid + p*256;
                pk[p] = *(const float4*)(Wk + (long)(kn + (lin >> 5))*DIM + n0 + 4*(lin & 31));
            }
        }

        #pragma unroll
        for (int kt = 0; kt < 2; ++kt) {
            uint32_t a[4];
            LDSM4(a[0],a[1],a[2],a[3], aQ + k0*2 + kt*32);
            #pragma unroll
            for (int jj = 0; jj < 2; ++jj) {
                uint32_t r0,r1,r2,r3;
                LDSM4T(r0,r1,r2,r3, bK[jj] + kt*16*272);
                MMA_F16(accK[2*jj],   a, r0, r1);
                MMA_F16(accK[2*jj+1], a, r2, r3);
            }
        }
        __syncthreads();
    }

    __half* out = Qkh + (long)b*KTOK*DIM;
    #pragma unroll
    for (int j = 0; j < 4; ++j) {
        int n = n0 + nw*32 + j*8 + 2*(lane & 3);
        __half2 h01 = __floats2half2_rn(accK[j][0], accK[j][1]);
        __half2 h23 = __floats2half2_rn(accK[j][2], accK[j][3]);
        *(uint32_t*)(out + (long)mrow*DIM + n)     = *(uint32_t*)&h01;
        *(uint32_t*)(out + (long)(mrow+8)*DIM + n) = *(uint32_t*)&h23;
    }
}

// ===========================================================================
// tail_gemm<KIN,NCOLS>: C[b][32, n0:n0+128] = A[b][32,KIN] @ W[n0:n0+128, KIN]^T
// 1024 threads = 4 warpgroups; warpgroup w owns k-quarter [w*KIN/4, (w+1)*KIN/4)
// (KIN/128 serial k-steps each), syncs via named barrier (id w+1, 256 thr).
// fp16 hi/lo (3 MMA). Partials reduced via smem. fp32 out.
// ===========================================================================
template<int KIN, int NCOLS>
__global__ __launch_bounds__(1024)
void tail_gemm(const float* __restrict__ Ag, const float* __restrict__ Wg,
               float* __restrict__ Cg)
{
    extern __shared__ __align__(16) unsigned char sm[];
    constexpr int PA     = KIN*2 + 16;
    constexpr int WOFF   = 64*PA;              // A hi (32*PA) + A lo (32*PA)
    constexpr int WSTRIDE= 20480;              // per-wg: hi 10240 + lo 10240
    constexpr int REDOFF = WOFF + 4*WSTRIDE;
    constexpr int KSTEPS = KIN/128;            // k32 steps per warpgroup

    const int n0 = blockIdx.x * 128;
    const int b  = blockIdx.y;
    const int tid  = threadIdx.x;
    const int lane = tid & 31;
    const int warp = tid >> 5;
    const int wg    = warp >> 3;      // 0..3
    const int wwarp = warp & 7;
    const int mw = wwarp >> 2;
    const int nw = wwarp & 3;
    const int wtid = tid & 255;

    const float* Ab = Ag + (long)b*KTOK*KIN;

    // ---- stage A[32,KIN] -> fp16 hi/lo (all 1024 threads) ----
    #pragma unroll
    for (int p = 0; p < KIN/128; ++p) {
        int lin = tid + p*1024;
        int r  = lin / (KIN/4);
        int c4 = lin % (KIN/4);
        float4 v = *(const float4*)(Ab + r*KIN + 4*c4);
        uint2 hi, lo; cvt_split4h(v, hi, lo);
        *(uint2*)(sm + r*PA + 8*c4)         = hi;
        *(uint2*)(sm + 32*PA + r*PA + 8*c4) = lo;
    }

    const int kbase = wg * (KIN/4);
    const uint32_t smb = cvta_s(sm);
    const uint32_t aH = smb + (mw*16 + (lane & 15))*PA + (lane >> 4)*16 + kbase*2;
    const uint32_t aL = aH + 32*PA;
    const uint32_t wbase = smb + WOFF + wg*WSTRIDE;
    uint32_t bH[2];
    #pragma unroll
    for (int jj = 0; jj < 2; ++jj)
        bH[jj] = wbase + (nw*32 + jj*16 + (lane & 7) + ((lane >> 4) & 1)*8)*80
               + ((lane >> 3) & 1)*16;

    // prefetch first W step (wg-private)
    float4 pw[4];
    #pragma unroll
    for (int p = 0; p < 4; ++p) {
        int lin = wtid + p*256;
        pw[p] = *(const float4*)(Wg + (long)(n0 + (lin >> 3))*KIN + kbase + 4*(lin & 7));
    }

    float acc[4][4];
    #pragma unroll
    for (int j = 0; j < 4; ++j)
        #pragma unroll
        for (int r = 0; r < 4; ++r) acc[j][r] = 0.f;

    __syncthreads();   // A planes visible

    for (int step = 0; step < KSTEPS; ++step) {
        // stage this step's W tile (wg-private buffer)
        #pragma unroll
        for (int p = 0; p < 4; ++p) {
            int lin = wtid + p*256;
            uint2 hi, lo; cvt_split4h(pw[p], hi, lo);
            *(uint2*)(sm + WOFF + wg*WSTRIDE + (lin >> 3)*80 + 8*(lin & 7))         = hi;
            *(uint2*)(sm + WOFF + wg*WSTRIDE + 10240 + (lin >> 3)*80 + 8*(lin & 7)) = lo;
        }
        asm volatile("bar.sync %0, %1;" :: "r"(wg+1), "r"(256) : "memory");

        if (step + 1 < KSTEPS) {
            int kn = kbase + (step+1)*32;
            #pragma unroll
            for (int p = 0; p < 4; ++p) {
                int lin = wtid + p*256;
                pw[p] = *(const float4*)(Wg + (long)(n0 + (lin >> 3))*KIN + kn + 4*(lin & 7));
            }
        }

        #pragma unroll
        for (int kt = 0; kt < 2; ++kt) {
            uint32_t ah[4], al[4];
            LDSM4(ah[0],ah[1],ah[2],ah[3], aH + step*64 + kt*32);
            LDSM4(al[0],al[1],al[2],al[3], aL + step*64 + kt*32);
            uint32_t bh[4][2], bl[4][2];
            #pragma unroll
            for (int jj = 0; jj < 2; ++jj) {
                uint32_t r0,r1,r2,r3;
                LDSM4(r0,r1,r2,r3, bH[jj] + kt*32);
                bh[2*jj][0]=r0; bh[2*jj][1]=r1; bh[2*jj+1][0]=r2; bh[2*jj+1][1]=r3;
                LDSM4(r0,r1,r2,r3, bH[jj] + 10240 + kt*32);
                bl[2*jj][0]=r0; bl[2*jj][1]=r1; bl[2*jj+1][0]=r2; bl[2*jj+1][1]=r3;
            }
            #pragma unroll
            for (int j = 0; j < 4; ++j) {
                MMA_F16(acc[j], ah, bh[j][0], bh[j][1]);
                MMA_F16(acc[j], ah, bl[j][0], bl[j][1]);
                MMA_F16(acc[j], al, bh[j][0], bh[j][1]);
            }
        }
        asm volatile("bar.sync %0, %1;" :: "r"(wg+1), "r"(256) : "memory");
    }

    // ---- write wg partials to smem ----
    {
        float* red = (float*)(sm + REDOFF) + wg*4096;
        const int mrow = mw*16 + (lane >> 2);
        #pragma unroll
        for (int j = 0; j < 4; ++j) {
            int c = nw*32 + j*8 + 2*(lane & 3);
            *(float2*)(red + mrow*128 + c)     = make_float2(acc[j][0], acc[j][1]);
            *(float2*)(red + (mrow+8)*128 + c) = make_float2(acc[j][2], acc[j][3]);
        }
    }
    __syncthreads();

    // ---- reduce across 4 wgs, write fp32 result ----
    {
        int e = tid * 4;                 // 4096 elems total
        int r = e >> 7, c = e & 127;
        const float* red = (const float*)(sm + REDOFF);
        float4 s = make_float4(0.f, 0.f, 0.f, 0.f);
        #pragma unroll
        for (int w = 0; w < 4; ++w) {
            float4 v = *(const float4*)(red + w*4096 + r*128 + c);
            s.x += v.x; s.y += v.y; s.z += v.z; s.w += v.w;
        }
        *(float4*)(Cg + ((long)b*KTOK + r)*NCOLS + n0 + c) = s;
    }
}

// ---------------------------------------------------------------------------
__global__ void normalize_rows(float* __restrict__ C)
{
    const int row = blockIdx.x;
    float* p = C + (long)row * DIM;
    const int t = threadIdx.x;
    float v[4]; float ss = 0.f;
    #pragma unroll
    for (int i = 0; i < 4; i++) { v[i] = p[t + i*128]; ss += v[i]*v[i]; }
    __shared__ float red[128];
    red[t] = ss; __syncthreads();
    #pragma unroll
    for (int s = 64; s > 0; s >>= 1) {
        if (t < s) red[t] += red[t+s];
        __syncthreads();
    }
    float inv = 1.f / (sqrtf(red[0]) + 1e-8f);
    #pragma unroll
    for (int i = 0; i < 4; i++) p[t + i*128] = v[i] * inv;
}

extern "C" void kernel_launch(void* const* d_in, const int* in_sizes, int n_in,
                              void* d_out, int out_size)
{
    const float* E  = (const float*)d_in[0];
    const float* T  = (const float*)d_in[1];
    const float* P  = (const float*)d_in[2];
    const float* Wq = (const float*)d_in[3];
    const float* Wk = (const float*)d_in[4];
    const float* Wv = (const float*)d_in[5];
    const float* Wo = (const float*)d_in[6];

    float* outF = (float*)d_out;
    float* outA = (float*)d_out + (long)BATCH*KTOK*DIM;

    float *pGp, *pG, *pF, *pRows;
    __half* pQkh;
    cudaGetSymbolAddress((void**)&pQkh,  g_Qkh);
    cudaGetSymbolAddress((void**)&pGp,   g_Gp);
    cudaGetSymbolAddress((void**)&pG,    g_G);
    cudaGetSymbolAddress((void**)&pF,    g_F);
    cudaGetSymbolAddress((void**)&pRows, g_rows);

    // smem sizes for tail_gemm instantiations
    const int TF_SMEM = 64*(512*2+16) + 4*20480 + 65536;   // KIN=512 -> 214016
    const int TO_SMEM = 64*(256*2+16) + 4*20480 + 65536;   // KIN=256 -> 181248

    cudaFuncSetAttribute(fused_attn4,
        cudaFuncAttributeMaxDynamicSharedMemorySize, SMEM_FUSED);
    cudaFuncSetAttribute(tail_gemm<512,256>,
        cudaFuncAttributeMaxDynamicSharedMemorySize, TF_SMEM);
    cudaFuncSetAttribute(tail_gemm<256,512>,
        cudaFuncAttributeMaxDynamicSharedMemorySize, TO_SMEM);

    dim3 blk(256);

    // 1) Qk = (T @ Wq^T) @ Wk  (merged, fp16 out)
    proj_qk<<<dim3(4, BATCH), blk>>>(T, Wq, Wk, pQkh);

    // 2) FUSED: expS/A(unnorm) + row-sum partials + G partials
    fused_attn4<<<dim3(SPLITS, BATCH), blk, SMEM_FUSED>>>(
        pQkh, E, P, outA, pGp, pRows);

    // 3) post: G reduce (256 blocks) + A row-scale (512 blocks)
    post_kernel<<<768, blk>>>(pGp, pG, pRows, outA);

    // 4) F = G @ Wv^T  (wide split-K-in-block, 32 blocks x 1024 thr)
    tail_gemm<512,256><<<dim3(2, BATCH), 1024, TF_SMEM>>>(pG, Wv, pF);

    // 5) out = F @ Wo^T  (wide split-K-in-block, 64 blocks x 1024 thr)
    tail_gemm<256,512><<<dim3(4, BATCH), 1024, TO_SMEM>>>(pF, Wo, outF);

    // 6) L2-normalize outF rows
    normalize_rows<<<BATCH*KTOK, 128>>>(outF);
}